// round 3
// baseline (speedup 1.0000x reference)
#include <cuda_runtime.h>
#include <math.h>

// Problem constants
#define B   256
#define L   512
#define I   32
#define H   16
#define G   64            // 4*H gates
#define NT  511           // number of increments
#define SIGD 4368         // H + H^2 + H^3
#define O   10

// Scratch (device globals; no allocation allowed)
static __device__ float g_xw[B * L * G];        // 33.5 MB : input projection + biases
static __device__ float g_d [B * NT * H];       // 8.4 MB  : h increments d_t = h_{t+1}-h_t

// ---------------------------------------------------------------------------
// Fast activations (ex2/rcp based, err ~1e-6) — exact enough, unchanged
// ---------------------------------------------------------------------------
__device__ __forceinline__ float sigmoidf_(float x) {
    return __fdividef(1.f, 1.f + __expf(-x));
}
__device__ __forceinline__ float tanhf_(float x) {
    float e = __expf(-2.f * fabsf(x));
    float r = __fdividef(1.f - e, 1.f + e);
    return copysignf(r, x);
}

// ---------------------------------------------------------------------------
// Packed fp32x2 helpers (Blackwell FFMA2 via PTX)
// ---------------------------------------------------------------------------
typedef unsigned long long u64t;
__device__ __forceinline__ u64t pack2_(float lo, float hi) {
    u64t r; asm("mov.b64 %0, {%1, %2};" : "=l"(r) : "f"(lo), "f"(hi)); return r;
}
__device__ __forceinline__ void unpack2_(u64t v, float& lo, float& hi) {
    asm("mov.b64 {%0, %1}, %2;" : "=f"(lo), "=f"(hi) : "l"(v));
}
__device__ __forceinline__ u64t ffma2_(u64t a, u64t b, u64t c) {
    u64t d; asm("fma.rn.f32x2 %0, %1, %2, %3;" : "=l"(d) : "l"(a), "l"(b), "l"(c));
    return d;
}

// ---------------------------------------------------------------------------
// K1: xw[bt][g] = b_ih[g] + b_hh[g] + sum_i X[bt][i] * W_ih[g][i]
// 128 bt-rows x 64 gates per 256-thread block.
// X pre-duplicated as (x,x) u64 pairs in shared (FFMA2 multiplier, no movs);
// W_ih transposed to [k][gate-quad] float4 (FFMA2 multiplicand pairs).
// ---------------------------------------------------------------------------
__global__ void __launch_bounds__(256) xw_kernel(const float* __restrict__ X,
                                                 const float* __restrict__ Wih,
                                                 const float* __restrict__ bih,
                                                 const float* __restrict__ bhh) {
    __shared__ __align__(16) u64t  Xs2[128 * 33];   // [row][k] dup pairs, pad 33
    __shared__ __align__(16) float4 Ws4[32 * 16];   // [k][q] = gates 4q..4q+3
    __shared__ float bs[64];

    int tid = threadIdx.x;
    int bt0 = blockIdx.x * 128;
    const float* Xg = X + (size_t)bt0 * I;

    for (int i = tid; i < 128 * I; i += 256) {
        int r = i >> 5, k = i & 31;
        float x = Xg[i];
        Xs2[r * 33 + k] = pack2_(x, x);
    }
    for (int i = tid; i < 512; i += 256) {        // transpose W_ih
        int k = i >> 4, q = i & 15;
        float4 w;
        w.x = Wih[(4 * q + 0) * I + k];
        w.y = Wih[(4 * q + 1) * I + k];
        w.z = Wih[(4 * q + 2) * I + k];
        w.w = Wih[(4 * q + 3) * I + k];
        Ws4[k * 16 + q] = w;
    }
    if (tid < 64) bs[tid] = bih[tid] + bhh[tid];
    __syncthreads();

    int tg = tid & 15;        // gate quad
    int tb = tid >> 4;        // row group of 8
    u64t acc[8][2];
    {
        u64t b0 = pack2_(bs[tg * 4 + 0], bs[tg * 4 + 1]);
        u64t b1 = pack2_(bs[tg * 4 + 2], bs[tg * 4 + 3]);
#pragma unroll
        for (int bi = 0; bi < 8; bi++) { acc[bi][0] = b0; acc[bi][1] = b1; }
    }

#pragma unroll 4
    for (int k = 0; k < I; k++) {
        float4 w4 = Ws4[k * 16 + tg];
        u64t wp0 = pack2_(w4.x, w4.y);
        u64t wp1 = pack2_(w4.z, w4.w);
        const u64t* xr = Xs2 + (tb * 8) * 33 + k;
#pragma unroll
        for (int bi = 0; bi < 8; bi++) {
            u64t xd = xr[bi * 33];
            acc[bi][0] = ffma2_(xd, wp0, acc[bi][0]);
            acc[bi][1] = ffma2_(xd, wp1, acc[bi][1]);
        }
    }

#pragma unroll
    for (int bi = 0; bi < 8; bi++) {
        int bt = bt0 + tb * 8 + bi;
        float4 v;
        unpack2_(acc[bi][0], v.x, v.y);
        unpack2_(acc[bi][1], v.z, v.w);
        *reinterpret_cast<float4*>(g_xw + (size_t)bt * G + tg * 4) = v;
    }
}

// ---------------------------------------------------------------------------
// K2: LSTM recurrence. One warp per TWO batch elements (lanes 0-15 / 16-31).
// Lane j owns h_j, c_j and computes ALL FOUR gate dots (i,f,g,o) for index j
// with packed f32x2 weights; h broadcast via width-16 shfl-gather (no smem,
// no syncs). 4-deep register prefetch of xw. Writes d_t = h_{t+1}-h_t.
// ---------------------------------------------------------------------------
__global__ void __launch_bounds__(32) lstm_kernel(const float* __restrict__ Whh) {
    int lane = threadIdx.x & 31;
    int half = lane >> 4;
    int j    = lane & 15;
    int batch = blockIdx.x * 2 + half;

    // packed W_hh rows: gate i -> row j, f -> 16+j, g -> 32+j, o -> 48+j
    u64t wi[8], wf[8], wg[8], wo[8];
    {
        const float2* wr;
        wr = reinterpret_cast<const float2*>(Whh + (j) * H);
#pragma unroll
        for (int m = 0; m < 8; m++) { float2 v = __ldg(wr + m); wi[m] = pack2_(v.x, v.y); }
        wr = reinterpret_cast<const float2*>(Whh + (16 + j) * H);
#pragma unroll
        for (int m = 0; m < 8; m++) { float2 v = __ldg(wr + m); wf[m] = pack2_(v.x, v.y); }
        wr = reinterpret_cast<const float2*>(Whh + (32 + j) * H);
#pragma unroll
        for (int m = 0; m < 8; m++) { float2 v = __ldg(wr + m); wg[m] = pack2_(v.x, v.y); }
        wr = reinterpret_cast<const float2*>(Whh + (48 + j) * H);
#pragma unroll
        for (int m = 0; m < 8; m++) { float2 v = __ldg(wr + m); wo[m] = pack2_(v.x, v.y); }
    }

    u64t hp[8];
#pragma unroll
    for (int m = 0; m < 8; m++) hp[m] = 0ull;
    float c = 0.f, hprev = 0.f;

    const float* xp = g_xw + (size_t)batch * (L * G);
    float* dp = g_d + (size_t)batch * (NT * H);

    // 4-deep prefetch of the 4 gate pre-activations
    float bx[4][4];
#pragma unroll
    for (int k = 0; k < 4; k++) {
        const float* p = xp + k * G;
        bx[k][0] = p[j]; bx[k][1] = p[j + 16]; bx[k][2] = p[j + 32]; bx[k][3] = p[j + 48];
    }

    for (int t = 0; t < L; t++) {
        int slot = t & 3;
        float xi = bx[slot][0], xf = bx[slot][1], xg = bx[slot][2], xo = bx[slot][3];
        if (t + 4 < L) {
            const float* p = xp + (t + 4) * G;
            bx[slot][0] = p[j]; bx[slot][1] = p[j + 16];
            bx[slot][2] = p[j + 32]; bx[slot][3] = p[j + 48];
        }

        u64t ai = 0ull, af = 0ull, ag = 0ull, ao = 0ull;
#pragma unroll
        for (int m = 0; m < 8; m++) {
            ai = ffma2_(hp[m], wi[m], ai);
            af = ffma2_(hp[m], wf[m], af);
            ag = ffma2_(hp[m], wg[m], ag);
            ao = ffma2_(hp[m], wo[m], ao);
        }
        float l0, h0;
        unpack2_(ai, l0, h0); float gi = xi + l0 + h0;
        unpack2_(af, l0, h0); float gf = xf + l0 + h0;
        unpack2_(ag, l0, h0); float gg = xg + l0 + h0;
        unpack2_(ao, l0, h0); float go = xo + l0 + h0;

        float si = sigmoidf_(gi);
        float sf = sigmoidf_(gf);
        float so = sigmoidf_(go);
        float tg = tanhf_(gg);
        c = fmaf(sf, c, si * tg);
        float hn = so * tanhf_(c);

        if (t) dp[(t - 1) * H + j] = hn - hprev;
        hprev = hn;

        // gather new h into packed pairs (width-16 shfl keeps batches separate)
#pragma unroll
        for (int m = 0; m < 8; m++) {
            float a = __shfl_sync(0xffffffffu, hn, 2 * m,     16);
            float bq = __shfl_sync(0xffffffffu, hn, 2 * m + 1, 16);
            hp[m] = pack2_(a, bq);
        }
    }
}

// ---------------------------------------------------------------------------
// K3: depth-3 signature scan + fused FC epilogue. One 256-thread CTA / batch.
// Thread tid = (a,b): S2[a][b] scalar, S3[a][b][0..15] as 8 packed f32x2.
// Rank-1 update: S3[a,b,:] += (S2 + S1*d[b]/2 + d[a]d[b]/6) * d[:]
// No per-step syncs; increments preloaded to shared (broadcast LDS).
// ---------------------------------------------------------------------------
__global__ void __launch_bounds__(256) sig_kernel(const float* __restrict__ fcw,
                                                  const float* __restrict__ fcb,
                                                  float* __restrict__ out) {
    __shared__ __align__(16) float ds[NT * H];   // 32704 B
    __shared__ float red[8][O];
    int bidx = blockIdx.x;
    int tid = threadIdx.x;

    {
        const float4* s4 = reinterpret_cast<const float4*>(g_d + (size_t)bidx * (NT * H));
        float4* t4 = reinterpret_cast<float4*>(ds);
        for (int i = tid; i < (NT * H) / 4; i += 256) t4[i] = s4[i];
    }
    __syncthreads();

    int a  = tid >> 4;
    int bb = tid & 15;

    float S1h = 0.f, S2 = 0.f;       // S1h = S1/2 (exact scaling)
    u64t S3p[8];
#pragma unroll
    for (int jq = 0; jq < 8; jq++) S3p[jq] = 0ull;

#pragma unroll 4
    for (int t = 0; t < NT; t++) {
        const float* dr = ds + t * H;
        float4 v0 = *reinterpret_cast<const float4*>(dr);
        float4 v1 = *reinterpret_cast<const float4*>(dr + 4);
        float4 v2 = *reinterpret_cast<const float4*>(dr + 8);
        float4 v3 = *reinterpret_cast<const float4*>(dr + 12);
        float db = dr[bb];
        float da = __shfl_sync(0xffffffffu, db, a, 16);   // dr[a]

        float m1   = da * db;
        float db2  = db + db;
        float coef = fmaf(S1h, db, fmaf(m1, (1.f / 6.f), S2));
        u64t cp = pack2_(coef, coef);

        S3p[0] = ffma2_(cp, pack2_(v0.x, v0.y), S3p[0]);
        S3p[1] = ffma2_(cp, pack2_(v0.z, v0.w), S3p[1]);
        S3p[2] = ffma2_(cp, pack2_(v1.x, v1.y), S3p[2]);
        S3p[3] = ffma2_(cp, pack2_(v1.z, v1.w), S3p[3]);
        S3p[4] = ffma2_(cp, pack2_(v2.x, v2.y), S3p[4]);
        S3p[5] = ffma2_(cp, pack2_(v2.z, v2.w), S3p[5]);
        S3p[6] = ffma2_(cp, pack2_(v3.x, v3.y), S3p[6]);
        S3p[7] = ffma2_(cp, pack2_(v3.z, v3.w), S3p[7]);

        S2  = fmaf(S1h, db2, fmaf(0.5f, m1, S2));
        S1h = fmaf(0.5f, da, S1h);
    }

    // ---- fused FC: out[b][o] = sig . fc_w[o] + fc_b[o] ----
    float S3[16];
#pragma unroll
    for (int jq = 0; jq < 8; jq++) unpack2_(S3p[jq], S3[2 * jq], S3[2 * jq + 1]);
    float S1 = S1h + S1h;

    float part[O];
#pragma unroll
    for (int o = 0; o < O; o++) {
        const float* wr = fcw + (size_t)o * SIGD;
        float acc = S2 * __ldg(wr + H + tid);              // level-2 term
        if (bb == 0) acc = fmaf(S1, __ldg(wr + a), acc);   // level-1 term
        const float4* w4 = reinterpret_cast<const float4*>(wr + H + H * H + tid * 16);
#pragma unroll
        for (int jq = 0; jq < 4; jq++) {
            float4 w = __ldg(w4 + jq);
            acc = fmaf(S3[4 * jq + 0], w.x, acc);
            acc = fmaf(S3[4 * jq + 1], w.y, acc);
            acc = fmaf(S3[4 * jq + 2], w.z, acc);
            acc = fmaf(S3[4 * jq + 3], w.w, acc);
        }
        part[o] = acc;
    }

    int lane = tid & 31, warp = tid >> 5;
#pragma unroll
    for (int off = 16; off > 0; off >>= 1)
#pragma unroll
        for (int o = 0; o < O; o++)
            part[o] += __shfl_down_sync(0xffffffffu, part[o], off);
    if (lane == 0)
#pragma unroll
        for (int o = 0; o < O; o++) red[warp][o] = part[o];
    __syncthreads();

    if (tid < O) {
        float v = fcb[tid];
#pragma unroll
        for (int w = 0; w < 8; w++) v += red[w][tid];
        out[bidx * O + tid] = v;
    }
}

// ---------------------------------------------------------------------------
extern "C" void kernel_launch(void* const* d_in, const int* in_sizes, int n_in,
                              void* d_out, int out_size) {
    const float* X   = (const float*)d_in[0];
    const float* Wih = (const float*)d_in[1];
    const float* Whh = (const float*)d_in[2];
    const float* bih = (const float*)d_in[3];
    const float* bhh = (const float*)d_in[4];
    const float* fcw = (const float*)d_in[5];
    const float* fcb = (const float*)d_in[6];
    float* out = (float*)d_out;

    xw_kernel<<<(B * L) / 128, 256>>>(X, Wih, bih, bhh);
    lstm_kernel<<<B / 2, 32>>>(Whh);
    sig_kernel<<<B, 256>>>(fcw, fcb, out);
}

// round 5
// speedup vs baseline: 2.9519x; 2.9519x over previous
#include <cuda_runtime.h>
#include <math.h>

// Problem constants
#define B   256
#define L   512
#define I   32
#define H   16
#define G   64            // 4*H gates
#define NT  511           // number of increments
#define SIGD 4368         // H + H^2 + H^3
#define O   10

// Scratch (device globals; no allocation allowed)
static __device__ float g_xw[B * L * G];        // 33.5 MB : input projection + biases
static __device__ float g_d [B * NT * H];       // 8.4 MB  : h increments d_t = h_{t+1}-h_t

// ---------------------------------------------------------------------------
// Activations via hardware MUFU.TANH (sm_75+): lat 16 vs ~40-45 for exp-based.
// sigmoid(x) = 0.5*tanh(x/2) + 0.5  (exact identity; only tanh is approx)
// ---------------------------------------------------------------------------
__device__ __forceinline__ float tanh_hw(float x) {
    float y; asm("tanh.approx.f32 %0, %1;" : "=f"(y) : "f"(x)); return y;
}
__device__ __forceinline__ float sigmoid_hw(float x) {
    return fmaf(tanh_hw(0.5f * x), 0.5f, 0.5f);
}

// ---------------------------------------------------------------------------
// Packed fp32x2 helpers (Blackwell FFMA2 via PTX) — used in sig kernel only
// ---------------------------------------------------------------------------
typedef unsigned long long u64t;
__device__ __forceinline__ u64t pack2_(float lo, float hi) {
    u64t r; asm("mov.b64 %0, {%1, %2};" : "=l"(r) : "f"(lo), "f"(hi)); return r;
}
__device__ __forceinline__ void unpack2_(u64t v, float& lo, float& hi) {
    asm("mov.b64 {%0, %1}, %2;" : "=f"(lo), "=f"(hi) : "l"(v));
}
__device__ __forceinline__ u64t ffma2_(u64t a, u64t b, u64t c) {
    u64t d; asm("fma.rn.f32x2 %0, %1, %2, %3;" : "=l"(d) : "l"(a), "l"(b), "l"(c));
    return d;
}

// ---------------------------------------------------------------------------
// K1: xw[bt][g] = b_ih[g] + b_hh[g] + sum_i X[bt][i] * W_ih[g][i]
// (round-2 version: measured 27.8us)
// ---------------------------------------------------------------------------
__global__ void __launch_bounds__(256) xw_kernel(const float* __restrict__ X,
                                                 const float* __restrict__ Wih,
                                                 const float* __restrict__ bih,
                                                 const float* __restrict__ bhh) {
    __shared__ float Xs[64 * 33];
    __shared__ float Ws[32 * 65];
    __shared__ float bs[64];

    int tid = threadIdx.x;
    int bt0 = blockIdx.x * 64;
    const float* Xg = X + (size_t)bt0 * I;

    for (int i = tid; i < 64 * I; i += 256) {
        int r = i >> 5, k = i & 31;
        Xs[r * 33 + k] = Xg[i];
        Ws[k * 65 + r] = Wih[i];
    }
    if (tid < 64) bs[tid] = bih[tid] + bhh[tid];
    __syncthreads();

    int tg = tid & 15;
    int tb = tid >> 4;
    float acc[4][4];
#pragma unroll
    for (int bi = 0; bi < 4; bi++)
#pragma unroll
        for (int gi = 0; gi < 4; gi++)
            acc[bi][gi] = bs[tg * 4 + gi];

#pragma unroll 8
    for (int k = 0; k < I; k++) {
        float xv[4], wv[4];
#pragma unroll
        for (int bi = 0; bi < 4; bi++) xv[bi] = Xs[(tb * 4 + bi) * 33 + k];
#pragma unroll
        for (int gi = 0; gi < 4; gi++) wv[gi] = Ws[k * 65 + tg * 4 + gi];
#pragma unroll
        for (int bi = 0; bi < 4; bi++)
#pragma unroll
            for (int gi = 0; gi < 4; gi++)
                acc[bi][gi] = fmaf(xv[bi], wv[gi], acc[bi][gi]);
    }

#pragma unroll
    for (int bi = 0; bi < 4; bi++) {
        int bt = bt0 + tb * 4 + bi;
        float4 v = make_float4(acc[bi][0], acc[bi][1], acc[bi][2], acc[bi][3]);
        *reinterpret_cast<float4*>(g_xw + (size_t)bt * G + tg * 4) = v;
    }
}

// ---------------------------------------------------------------------------
// K2: LSTM recurrence (round-2 structure: one warp per batch, lane l computes
// gate rows l and l+32, shfl gate exchange, smem h broadcast, 4-deep prefetch).
// ONLY change vs round-2: hardware tanh activations (chain ~215 -> ~165 cyc).
// ---------------------------------------------------------------------------
__global__ void __launch_bounds__(128) lstm_kernel(const float* __restrict__ Whh) {
    __shared__ __align__(16) float hsm[4][2][16];
    int lane = threadIdx.x & 31;
    int warp = threadIdx.x >> 5;
    int b = blockIdx.x * 4 + warp;

    float w0[H], w1[H];
#pragma unroll
    for (int j = 0; j < H; j++) {
        w0[j] = __ldg(Whh + lane * H + j);
        w1[j] = __ldg(Whh + (lane + 32) * H + j);
    }
    float h[H];
#pragma unroll
    for (int j = 0; j < H; j++) h[j] = 0.f;
    float c = 0.f, hprev = 0.f;

    const float* xp = g_xw + (size_t)b * (L * G) + lane;
    float* dp = g_d + (size_t)b * (NT * H);

    float bx0[4], bx1[4];
#pragma unroll
    for (int k = 0; k < 4; k++) { bx0[k] = xp[k * G]; bx1[k] = xp[k * G + 32]; }

#pragma unroll 4
    for (int t = 0; t < L; t++) {
        int slot = t & 3;
        float a0 = bx0[slot], a1 = bx1[slot];
        if (t + 4 < L) { bx0[slot] = xp[(t + 4) * G]; bx1[slot] = xp[(t + 4) * G + 32]; }

        float q0 = 0.f, q1 = 0.f;
#pragma unroll
        for (int j = 0; j < 8; j++) {
            a0 = fmaf(h[j],     w0[j],     a0);
            q0 = fmaf(h[j + 8], w0[j + 8], q0);
            a1 = fmaf(h[j],     w1[j],     a1);
            q1 = fmaf(h[j + 8], w1[j + 8], q1);
        }
        a0 += q0; a1 += q1;

        float fg = __shfl_down_sync(0xffffffffu, a0, 16);  // lanes<16: f preact
        float og = __shfl_down_sync(0xffffffffu, a1, 16);  // lanes<16: o preact

        float si = sigmoid_hw(a0);
        float sf = sigmoid_hw(fg);
        float so = sigmoid_hw(og);
        float tg = tanh_hw(a1);
        c = fmaf(sf, c, si * tg);
        float hn = so * tanh_hw(c);

        int buf = t & 1;
        if (lane < H) {
            hsm[warp][buf][lane] = hn;
            if (t) dp[(t - 1) * H + lane] = hn - hprev;
            hprev = hn;
        }
        __syncwarp();
#pragma unroll
        for (int j = 0; j < H; j += 4) {
            float4 v = *reinterpret_cast<const float4*>(&hsm[warp][buf][j]);
            h[j] = v.x; h[j + 1] = v.y; h[j + 2] = v.z; h[j + 3] = v.w;
        }
    }
}

// ---------------------------------------------------------------------------
// K3: depth-3 signature scan + fused FC epilogue (round-2 version, unchanged).
// ---------------------------------------------------------------------------
__global__ void __launch_bounds__(256) sig_kernel(const float* __restrict__ fcw,
                                                  const float* __restrict__ fcb,
                                                  float* __restrict__ out) {
    __shared__ __align__(16) float ds[NT * H];   // 32704 B
    __shared__ float red[8][O];
    int bidx = blockIdx.x;
    int tid = threadIdx.x;

    {
        const float4* s4 = reinterpret_cast<const float4*>(g_d + (size_t)bidx * (NT * H));
        float4* t4 = reinterpret_cast<float4*>(ds);
        for (int i = tid; i < (NT * H) / 4; i += 256) t4[i] = s4[i];
    }
    __syncthreads();

    int a  = tid >> 4;
    int bb = tid & 15;

    float S1h = 0.f, S2 = 0.f;       // S1h = S1/2 (exact scaling)
    u64t S3p[8];
#pragma unroll
    for (int j = 0; j < 8; j++) S3p[j] = 0ull;

#pragma unroll 2
    for (int t = 0; t < NT; t++) {
        const float* dr = ds + t * H;
        float4 v0 = *reinterpret_cast<const float4*>(dr);
        float4 v1 = *reinterpret_cast<const float4*>(dr + 4);
        float4 v2 = *reinterpret_cast<const float4*>(dr + 8);
        float4 v3 = *reinterpret_cast<const float4*>(dr + 12);
        float da = dr[a];
        float db = dr[bb];

        float m1   = da * db;
        float db2  = db + db;
        float coef = fmaf(S1h, db, fmaf(m1, (1.f / 6.f), S2));
        u64t cp = pack2_(coef, coef);

        S3p[0] = ffma2_(cp, pack2_(v0.x, v0.y), S3p[0]);
        S3p[1] = ffma2_(cp, pack2_(v0.z, v0.w), S3p[1]);
        S3p[2] = ffma2_(cp, pack2_(v1.x, v1.y), S3p[2]);
        S3p[3] = ffma2_(cp, pack2_(v1.z, v1.w), S3p[3]);
        S3p[4] = ffma2_(cp, pack2_(v2.x, v2.y), S3p[4]);
        S3p[5] = ffma2_(cp, pack2_(v2.z, v2.w), S3p[5]);
        S3p[6] = ffma2_(cp, pack2_(v3.x, v3.y), S3p[6]);
        S3p[7] = ffma2_(cp, pack2_(v3.z, v3.w), S3p[7]);

        S2  = fmaf(S1h, db2, fmaf(0.5f, m1, S2));
        S1h = fmaf(0.5f, da, S1h);
    }

    // ---- fused FC: out[b][o] = sig . fc_w[o] + fc_b[o] ----
    float S3[16];
#pragma unroll
    for (int j = 0; j < 8; j++) unpack2_(S3p[j], S3[2 * j], S3[2 * j + 1]);
    float S1 = S1h + S1h;

    float part[O];
#pragma unroll
    for (int o = 0; o < O; o++) {
        const float* wr = fcw + (size_t)o * SIGD;
        float acc = S2 * __ldg(wr + H + tid);              // level-2 term
        if (bb == 0) acc = fmaf(S1, __ldg(wr + a), acc);   // level-1 term
        const float4* w4 = reinterpret_cast<const float4*>(wr + H + H * H + tid * 16);
#pragma unroll
        for (int j = 0; j < 4; j++) {
            float4 w = __ldg(w4 + j);
            acc = fmaf(S3[4 * j + 0], w.x, acc);
            acc = fmaf(S3[4 * j + 1], w.y, acc);
            acc = fmaf(S3[4 * j + 2], w.z, acc);
            acc = fmaf(S3[4 * j + 3], w.w, acc);
        }
        part[o] = acc;
    }

    int lane = tid & 31, warp = tid >> 5;
#pragma unroll
    for (int off = 16; off > 0; off >>= 1)
#pragma unroll
        for (int o = 0; o < O; o++)
            part[o] += __shfl_down_sync(0xffffffffu, part[o], off);
    if (lane == 0)
#pragma unroll
        for (int o = 0; o < O; o++) red[warp][o] = part[o];
    __syncthreads();

    if (tid < O) {
        float v = fcb[tid];
#pragma unroll
        for (int w = 0; w < 8; w++) v += red[w][tid];
        out[bidx * O + tid] = v;
    }
}

// ---------------------------------------------------------------------------
extern "C" void kernel_launch(void* const* d_in, const int* in_sizes, int n_in,
                              void* d_out, int out_size) {
    const float* X   = (const float*)d_in[0];
    const float* Wih = (const float*)d_in[1];
    const float* Whh = (const float*)d_in[2];
    const float* bih = (const float*)d_in[3];
    const float* bhh = (const float*)d_in[4];
    const float* fcw = (const float*)d_in[5];
    const float* fcb = (const float*)d_in[6];
    float* out = (float*)d_out;

    xw_kernel<<<(B * L) / 64, 256>>>(X, Wih, bih, bhh);
    lstm_kernel<<<B / 4, 128>>>(Whh);
    sig_kernel<<<B, 256>>>(fcw, fcb, out);
}